// round 11
// baseline (speedup 1.0000x reference)
#include <cuda_runtime.h>

#define D 128
#define MAXN 50000
#define MAXE 800000

typedef unsigned long long u64;

// ---------------- scratch (device globals; resolve via cudaGetSymbolAddress
// when passed as kernel args -- host-side &sym is the ATS host shadow!) ------
__device__ float g_h[(size_t)MAXN * D];
__device__ float g_t[(size_t)MAXN * D];
__device__ float g_dinv[MAXN];
__device__ int   g_deg[MAXN];
__device__ int   g_rowptr[MAXN + 1];
__device__ int   g_cursor[MAXN];
__device__ int   g_col[MAXE];
__device__ float g_wgt[MAXE];
__device__ int   g_bsum[64];
__device__ int   g_boff[64];

// ---------------- f32x2 packed-FMA helpers ---------------------------------
__device__ __forceinline__ u64 fma2(u64 a, u64 b, u64 c) {
    u64 d;
    asm("fma.rn.f32x2 %0, %1, %2, %3;" : "=l"(d) : "l"(a), "l"(b), "l"(c));
    return d;
}
__device__ __forceinline__ u64 dup2(float v) {
    u64 d; unsigned u = __float_as_uint(v);
    asm("mov.b64 %0, {%1, %1};" : "=l"(d) : "r"(u));
    return d;
}

// ---------------- prep -------------------------------------------------------
__global__ void k_zero(int n) {
    int i = blockIdx.x * blockDim.x + threadIdx.x;
    if (i < n) g_deg[i] = 0;
}

__global__ void k_count(const int* __restrict__ dst, int e) {
    int i = blockIdx.x * blockDim.x + threadIdx.x;
    if (i < e) atomicAdd(&g_deg[dst[i]], 1);
}

// Pass 1: per-1024-block local inclusive scan of deg (+ dinv folded).
__global__ void k_scan1(int n) {
    __shared__ int warpsum[32];
    int tid = threadIdx.x, lane = tid & 31, wid = tid >> 5;
    int i = blockIdx.x * 1024 + tid;
    int v = (i < n) ? g_deg[i] : 0;
    if (i < n) g_dinv[i] = rsqrtf((float)(v + 1));   // +1 self loop
    int incl = v;
    #pragma unroll
    for (int off = 1; off < 32; off <<= 1) {
        int t = __shfl_up_sync(0xffffffffu, incl, off);
        if (lane >= off) incl += t;
    }
    if (lane == 31) warpsum[wid] = incl;
    __syncthreads();
    if (wid == 0) {
        int ws = warpsum[lane];
        int wincl = ws;
        #pragma unroll
        for (int off = 1; off < 32; off <<= 1) {
            int t = __shfl_up_sync(0xffffffffu, wincl, off);
            if (lane >= off) wincl += t;
        }
        warpsum[lane] = wincl - ws;
    }
    __syncthreads();
    incl += warpsum[wid];
    if (i < n) g_rowptr[i + 1] = incl;
    if (tid == 1023) g_bsum[blockIdx.x] = incl;
}

// Pass 2: exclusive scan of <=64 block sums.
__global__ void k_scan2(int nb) {
    __shared__ int w0tot;
    int tid = threadIdx.x, lane = tid & 31, wid = tid >> 5;
    int v = (tid < nb) ? g_bsum[tid] : 0;
    int incl = v;
    #pragma unroll
    for (int off = 1; off < 32; off <<= 1) {
        int t = __shfl_up_sync(0xffffffffu, incl, off);
        if (lane >= off) incl += t;
    }
    if (wid == 0 && lane == 31) w0tot = incl;
    __syncthreads();
    if (wid == 1) incl += w0tot;
    if (tid < nb) g_boff[tid] = incl - v;
    if (tid == 0) g_rowptr[0] = 0;
}

// Pass 3: apply block offsets.
__global__ void k_scan3(int n) {
    int i = blockIdx.x * 1024 + threadIdx.x;
    if (i < n) {
        int r = g_rowptr[i + 1] + g_boff[blockIdx.x];
        g_rowptr[i + 1] = r;
        g_cursor[i] = r - g_deg[i];
    }
}

__global__ void k_fill(const int* __restrict__ src, const int* __restrict__ dst, int e) {
    int i = blockIdx.x * blockDim.x + threadIdx.x;
    if (i < e) {
        int s = src[i], d = dst[i];
        int pos = atomicAdd(&g_cursor[d], 1);
        g_col[pos] = s;
        g_wgt[pos] = g_dinv[s] * g_dinv[d];
    }
}

// ---------------- GEMM: T[n,128] = H[n,128] @ W[128,128] --------------------
// Retiled for occupancy: block = 64 rows x 64 cols (half of W).
// smem = W-half 32KB + H-tile 32KB = 64KB -> 3 CTAs/SM (24 warps, was 16).
// Thread: 8 rows x 2 cols (u64 packed accumulators), warp: 8 rows x 64 cols.
#define GEMM_ROWS 64
#define GEMM_COLS 64
#define GEMM_SMEM ((D * GEMM_COLS + GEMM_ROWS * D) * 4)

__global__ __launch_bounds__(256, 3) void k_gemm(
    const float* __restrict__ H, const float* __restrict__ W,
    float* __restrict__ T, int n)
{
    extern __shared__ float smem[];
    float* sW = smem;                    // [128][64]
    float* sH = smem + D * GEMM_COLS;    // [64][128]
    int tid = threadIdx.x;

    int ch   = blockIdx.x & 1;           // column half: 0 or 1
    int row0 = (blockIdx.x >> 1) * GEMM_ROWS;

    // Load W half: 128 rows x 16 float4
    {
        float4* sW4 = (float4*)sW;
        const float4* W4 = (const float4*)W;
        #pragma unroll
        for (int i = tid; i < D * GEMM_COLS / 4; i += 256) {
            int k  = i >> 4;             // 16 float4 per row
            int c4 = i & 15;
            sW4[i] = W4[k * 32 + ch * 16 + c4];
        }
    }
    // Load H tile: 64 rows x 32 float4
    {
        float4* sH4 = (float4*)sH;
        #pragma unroll
        for (int i = tid; i < GEMM_ROWS * D / 4; i += 256) {
            int r  = i >> 5;
            int c4 = i & 31;
            int gr = row0 + r;
            float4 v = make_float4(0.f, 0.f, 0.f, 0.f);
            if (gr < n) v = ((const float4*)(H + (size_t)gr * D))[c4];
            sH4[i] = v;
        }
    }
    __syncthreads();

    int warp = tid >> 5, lane = tid & 31;
    int rbase = warp * 8;

    u64 acc[8];
    #pragma unroll
    for (int r = 0; r < 8; r++) acc[r] = 0ull;

    const u64* sW64 = (const u64*)sW;    // [k][32] u64 (2 cols each)

    #pragma unroll 2
    for (int k4 = 0; k4 < D; k4 += 4) {
        u64 wv[4];
        #pragma unroll
        for (int kk = 0; kk < 4; kk++) wv[kk] = sW64[(k4 + kk) * 32 + lane];
        float4 hv[8];
        #pragma unroll
        for (int r = 0; r < 8; r++)
            hv[r] = *(const float4*)&sH[(rbase + r) * D + k4];
        #pragma unroll
        for (int kk = 0; kk < 4; kk++) {
            #pragma unroll
            for (int r = 0; r < 8; r++) {
                float h = (kk == 0) ? hv[r].x : (kk == 1) ? hv[r].y
                        : (kk == 2) ? hv[r].z : hv[r].w;
                acc[r] = fma2(dup2(h), wv[kk], acc[r]);
            }
        }
    }

    #pragma unroll
    for (int r = 0; r < 8; r++) {
        int gr = row0 + rbase + r;
        if (gr < n)
            ((u64*)(T + (size_t)gr * D + ch * GEMM_COLS))[lane] = acc[r];
    }
}

// ---------------- Aggregation: warp per node (CSR gather, no atomics) -------
__global__ __launch_bounds__(256) void k_agg(
    const float* __restrict__ T, const float* __restrict__ bias,
    const float* __restrict__ X, float* __restrict__ OUT,
    int n, int do_relu)
{
    int gw = (blockIdx.x * blockDim.x + threadIdx.x) >> 5;
    int lane = threadIdx.x & 31;
    if (gw >= n) return;

    int beg = g_rowptr[gw];
    int end = g_rowptr[gw + 1];
    float di = g_dinv[gw];

    const float4* T4 = (const float4*)T;
    float4 tv = T4[(size_t)gw * 32 + lane];
    float sw = di * di;
    float4 acc = make_float4(tv.x * sw, tv.y * sw, tv.z * sw, tv.w * sw);

    int e = beg;
    for (; e + 4 <= end; e += 4) {
        int s0 = g_col[e], s1 = g_col[e + 1], s2 = g_col[e + 2], s3 = g_col[e + 3];
        float w0 = g_wgt[e], w1 = g_wgt[e + 1], w2 = g_wgt[e + 2], w3 = g_wgt[e + 3];
        float4 a = T4[(size_t)s0 * 32 + lane];
        float4 b = T4[(size_t)s1 * 32 + lane];
        float4 c = T4[(size_t)s2 * 32 + lane];
        float4 d = T4[(size_t)s3 * 32 + lane];
        acc.x = fmaf(w0, a.x, acc.x); acc.y = fmaf(w0, a.y, acc.y);
        acc.z = fmaf(w0, a.z, acc.z); acc.w = fmaf(w0, a.w, acc.w);
        acc.x = fmaf(w1, b.x, acc.x); acc.y = fmaf(w1, b.y, acc.y);
        acc.z = fmaf(w1, b.z, acc.z); acc.w = fmaf(w1, b.w, acc.w);
        acc.x = fmaf(w2, c.x, acc.x); acc.y = fmaf(w2, c.y, acc.y);
        acc.z = fmaf(w2, c.z, acc.z); acc.w = fmaf(w2, c.w, acc.w);
        acc.x = fmaf(w3, d.x, acc.x); acc.y = fmaf(w3, d.y, acc.y);
        acc.z = fmaf(w3, d.z, acc.z); acc.w = fmaf(w3, d.w, acc.w);
    }
    for (; e < end; e++) {
        int s = g_col[e];
        float w = g_wgt[e];
        float4 a = T4[(size_t)s * 32 + lane];
        acc.x = fmaf(w, a.x, acc.x); acc.y = fmaf(w, a.y, acc.y);
        acc.z = fmaf(w, a.z, acc.z); acc.w = fmaf(w, a.w, acc.w);
    }

    float4 bv = ((const float4*)bias)[lane];
    acc.x += bv.x; acc.y += bv.y; acc.z += bv.z; acc.w += bv.w;

    if (do_relu) {
        acc.x = fmaxf(acc.x, 0.f); acc.y = fmaxf(acc.y, 0.f);
        acc.z = fmaxf(acc.z, 0.f); acc.w = fmaxf(acc.w, 0.f);
    }
    if (X) {
        float4 xv = ((const float4*)X)[(size_t)gw * 32 + lane];
        acc.x += xv.x; acc.y += xv.y; acc.z += xv.z; acc.w += xv.w;
    }
    ((float4*)OUT)[(size_t)gw * 32 + lane] = acc;
}

// ---------------- launch ----------------------------------------------------
extern "C" void kernel_launch(void* const* d_in, const int* in_sizes, int n_in,
                              void* d_out, int out_size)
{
    const float* x  = (const float*)d_in[0];
    const int*   ei = (const int*)d_in[1];
    const float* W0 = (const float*)d_in[2];
    const float* b0 = (const float*)d_in[3];
    const float* W1 = (const float*)d_in[4];
    const float* b1 = (const float*)d_in[5];
    const float* W2 = (const float*)d_in[6];
    const float* b2 = (const float*)d_in[7];
    float* out = (float*)d_out;

    int n = in_sizes[0] / D;
    int e = in_sizes[1] / 2;
    const int* src = ei;
    const int* dst = ei + e;

    // True DEVICE addresses of scratch (ATS host-shadow trap).
    float *dT = nullptr, *dH = nullptr;
    cudaGetSymbolAddress((void**)&dT, g_t);
    cudaGetSymbolAddress((void**)&dH, g_h);

    cudaFuncSetAttribute(k_gemm, cudaFuncAttributeMaxDynamicSharedMemorySize, GEMM_SMEM);

    static cudaStream_t s_side = nullptr;
    static cudaEvent_t ev_fork = nullptr, ev_join = nullptr;
    if (!s_side) {
        cudaStreamCreateWithFlags(&s_side, cudaStreamNonBlocking);
        cudaEventCreateWithFlags(&ev_fork, cudaEventDisableTiming);
        cudaEventCreateWithFlags(&ev_join, cudaEventDisableTiming);
    }

    int tb = 256;
    int gn = (n + tb - 1) / tb;
    int ge = (e + tb - 1) / tb;
    int nb = (n + 1023) / 1024;
    int ggemm = 2 * ((n + GEMM_ROWS - 1) / GEMM_ROWS);   // x2 column halves
    int gagg  = (n + 7) / 8;

    cudaEventRecord(ev_fork, 0);

    // Main stream: CSR/norm prep
    k_zero <<<gn, tb>>>(n);                    // #1
    k_count<<<ge, tb>>>(dst, e);               // #2
    k_scan1<<<nb, 1024>>>(n);                  // #3

    // Side stream: GEMM0 (profiled as submission #4)
    cudaStreamWaitEvent(s_side, ev_fork, 0);
    k_gemm<<<ggemm, tb, GEMM_SMEM, s_side>>>(x, W0, dT, n);   // #4
    cudaEventRecord(ev_join, s_side);

    k_scan2<<<1, 64>>>(nb);                    // #5
    k_scan3<<<nb, 1024>>>(n);                  // #6
    k_fill <<<ge, tb>>>(src, dst, e);          // #7

    cudaStreamWaitEvent(0, ev_join, 0);
    k_agg<<<gagg, tb>>>(dT, b0, nullptr, dH, n, 1);           // #8

    k_gemm<<<ggemm, tb, GEMM_SMEM>>>(dH, W1, dT, n);          // #9
    k_agg<<<gagg, tb>>>(dT, b1, nullptr, dH, n, 1);           // #10

    k_gemm<<<ggemm, tb, GEMM_SMEM>>>(dH, W2, dT, n);          // #11
    k_agg<<<gagg, tb>>>(dT, b2, x, out, n, 0);                // #12
}